// round 7
// baseline (speedup 1.0000x reference)
#include <cuda_runtime.h>

// Problem dims (fixed by setup_inputs)
#define Bv   1024
#define Tv   80
#define Dv   300
#define Hv   300
#define G4   1200           // 4*H
#define NBLK 570            // 4/SM co-resident (46KB smem)
#define NTHR 128

// Scratch (device globals — no allocation allowed)
__device__ float g_xpre[(size_t)Tv * G4 * Bv];   // xpre[t][n][p]
__device__ float g_hT[2][Hv * Bv];               // hT[k][p], double buffered
__device__ float g_cT[Hv * Bv];                  // cT[j][p]
__device__ float4 g_whT[Hv * Hv];                // whT[k*H+j] = 4 gate weights
__device__ int   g_perm[Bv];
__device__ int   g_rank[Bv];
__device__ int   g_act[Tv];
__device__ int   g_ctr[Tv][152];                 // per-(step, j-tile) work tickets
__device__ unsigned g_bar_count;
__device__ unsigned g_bar_sense;

// ---------------------------------------------------------------------------
__global__ void init_kernel(const int* __restrict__ lens) {
    __shared__ int sl[Bv];
    const int tid = threadIdx.x;
    sl[tid] = lens[tid];
    __syncthreads();
    const int L = sl[tid];
    int r = 0;
    for (int b = 0; b < Bv; b++) {
        int L2 = sl[b];
        r += (L2 > L) || (L2 == L && b < tid);
    }
    g_rank[tid] = r;
    g_perm[r]   = tid;
    if (tid < Tv) {
        int c = 0;
        for (int b = 0; b < Bv; b++) c += (sl[b] > tid);
        g_act[tid] = c;
    }
    if (tid == 0) { g_bar_count = 0; g_bar_sense = 0; }
}

__global__ void zero_kernel() {
    int i = blockIdx.x * blockDim.x + threadIdx.x;
    if (i < Hv * Bv) {
        g_hT[0][i] = 0.f;
        g_hT[1][i] = 0.f;
        g_cT[i]    = 0.f;
    }
    if (i < Tv * 152) ((int*)g_ctr)[i] = 0;      // reset work tickets
}

// Transpose Wh[k][g*H+j] -> whT[k*H+j] = float4(g0,g1,g2,g3)
__global__ void trans_kernel(const float* __restrict__ Wh) {
    int i = blockIdx.x * blockDim.x + threadIdx.x;
    if (i < Hv * Hv) {
        int k = i / Hv, j = i - k * Hv;
        const float* r = Wh + k * G4 + j;
        g_whT[i] = make_float4(r[0], r[Hv], r[2 * Hv], r[3 * Hv]);
    }
}

// ---------------------------------------------------------------------------
// Precompute xpre[t][n][p]
// ---------------------------------------------------------------------------
__global__ __launch_bounds__(256, 2) void pre_kernel(
    const int*   __restrict__ sent,
    const float* __restrict__ emb,
    const float* __restrict__ Wx,
    const float* __restrict__ bias)
{
    const int t  = blockIdx.z;
    const int p0 = blockIdx.x * 128;
    const int n0 = blockIdx.y * 128;
    if (p0 >= g_act[t]) return;

    __shared__ int   idxs[128];
    __shared__ __align__(16) float es[20][128];
    __shared__ __align__(16) float ws[20][128];

    const int tid = threadIdx.x;
    const int tx  = tid & 15;
    const int ty  = tid >> 4;

    if (tid < 128) idxs[tid] = sent[g_perm[p0 + tid] * Tv + t];
    __syncthreads();

    float acc[8][8];
#pragma unroll
    for (int i = 0; i < 8; i++)
#pragma unroll
        for (int j = 0; j < 8; j++) acc[i][j] = 0.f;

    for (int k0 = 0; k0 < Dv; k0 += 20) {
#pragma unroll
        for (int r = 0; r < 10; r++) {
            int f  = r * 256 + tid;
            int rl = f & 127;
            int kl = f >> 7;
            es[kl][rl] = emb[(size_t)idxs[rl] * Dv + k0 + kl];
            int n = n0 + rl;
            ws[kl][rl] = (n < G4) ? Wx[(k0 + kl) * G4 + n] : 0.f;
        }
        __syncthreads();
#pragma unroll
        for (int k = 0; k < 20; k++) {
            float4 a0 = *(const float4*)&es[k][tx * 4];
            float4 a1 = *(const float4*)&es[k][tx * 4 + 64];
            float4 w0 = *(const float4*)&ws[k][ty * 4];
            float4 w1 = *(const float4*)&ws[k][ty * 4 + 64];
            float a[8] = {a0.x, a0.y, a0.z, a0.w, a1.x, a1.y, a1.z, a1.w};
            float w[8] = {w0.x, w0.y, w0.z, w0.w, w1.x, w1.y, w1.z, w1.w};
#pragma unroll
            for (int ni = 0; ni < 8; ni++)
#pragma unroll
                for (int pi = 0; pi < 8; pi++)
                    acc[ni][pi] = fmaf(w[ni], a[pi], acc[ni][pi]);
        }
        __syncthreads();
    }

#pragma unroll
    for (int ni = 0; ni < 8; ni++) {
        int n = n0 + (ni >> 2) * 64 + ty * 4 + (ni & 3);
        if (n >= G4) continue;
        float bn = bias[n];
        size_t base = ((size_t)t * G4 + n) * Bv + p0;
        float4 v0 = make_float4(acc[ni][0] + bn, acc[ni][1] + bn,
                                acc[ni][2] + bn, acc[ni][3] + bn);
        float4 v1 = make_float4(acc[ni][4] + bn, acc[ni][5] + bn,
                                acc[ni][6] + bn, acc[ni][7] + bn);
        *(float4*)&g_xpre[base + tx * 4]      = v0;
        *(float4*)&g_xpre[base + tx * 4 + 64] = v1;
    }
}

// ---------------------------------------------------------------------------
// Persistent LSTM recurrence: Wh phase-resident in smem, dynamic p-tile grab.
// ---------------------------------------------------------------------------
__device__ __forceinline__ float sigmoidf_(float x) {
    return 1.f / (1.f + __expf(-x));
}
__device__ __forceinline__ float tanhf_(float x) {
    return 1.f - 2.f / (__expf(2.f * x) + 1.f);
}

__device__ __forceinline__ void grid_barrier(unsigned target) {
    __threadfence();
    __syncthreads();
    if (threadIdx.x == 0) {
        if (atomicAdd(&g_bar_count, 1u) == NBLK - 1) {
            g_bar_count = 0;
            __threadfence();
            atomicExch(&g_bar_sense, target);
        } else {
            while (*(volatile unsigned*)&g_bar_sense < target) __nanosleep(32);
        }
    }
    __syncthreads();
}

// One tile: 64 p x W j-cols x 4 gates, 128 threads. Wh resident in ws4.
// Only h is staged per 15-k chunk (double-buffered, 1 sync per chunk).
template<int W>
__device__ __forceinline__ void step_tile_full(
    float hs[2][15][64], const float4* __restrict__ ws4,
    const float* __restrict__ hin, float* __restrict__ hout,
    int t, int p0, int j0, int act)
{
    constexpr int TPJ = NTHR / W;
    constexpr int PPT = 64 / TPJ;
    const int tid  = threadIdx.x;
    const int pidx = tid % TPJ;
    const int jc   = tid / TPJ;
    const int j    = j0 + jc;

    float4 ph[2];
    auto load_c = [&](int k0) {
#pragma unroll
        for (int i = 0; i < 2; i++) {
            int f = i * NTHR + tid;
            if (f < 240)
                ph[i] = __ldcg((const float4*)&hin[(k0 + (f >> 4)) * Bv + p0
                                                   + ((f & 15) << 2)]);
        }
    };
    auto store_c = [&](int buf) {
#pragma unroll
        for (int i = 0; i < 2; i++) {
            int f = i * NTHR + tid;
            if (f < 240)
                *(float4*)&hs[buf][f >> 4][(f & 15) << 2] = ph[i];
        }
    };

    float acc[PPT][4];
#pragma unroll
    for (int p = 0; p < PPT; p++)
#pragma unroll
        for (int g = 0; g < 4; g++) acc[p][g] = 0.f;

    load_c(0);
    store_c(0);
    __syncthreads();

#pragma unroll 1
    for (int c = 0; c < 20; c++) {
        const int cur = c & 1;
        if (c < 19) load_c((c + 1) * 15);
#pragma unroll
        for (int kk = 0; kk < 15; kk++) {
            const int k = c * 15 + kk;
            float hv[PPT];
            if (PPT == 4) {
                float4 h4 = *(const float4*)&hs[cur][kk][pidx * 4];
                hv[0] = h4.x; hv[1] = h4.y; hv[2] = h4.z; hv[3] = h4.w;
            } else if (PPT == 2) {
                float2 h2 = *(const float2*)&hs[cur][kk][pidx * 2];
                hv[0] = h2.x; hv[1] = h2.y;
            } else {
                hv[0] = hs[cur][kk][pidx];
            }
            float4 w4 = ws4[k * W + jc];
#pragma unroll
            for (int p = 0; p < PPT; p++) {
                acc[p][0] = fmaf(hv[p], w4.x, acc[p][0]);
                acc[p][1] = fmaf(hv[p], w4.y, acc[p][1]);
                acc[p][2] = fmaf(hv[p], w4.z, acc[p][2]);
                acc[p][3] = fmaf(hv[p], w4.w, acc[p][3]);
            }
        }
        if (c < 19) { store_c(cur ^ 1); __syncthreads(); }
    }

    if (j < Hv) {
        const size_t tb = (size_t)t * G4;
        const int pb = p0 + pidx * PPT;
        const int hi = j * Bv + pb;

        if (PPT == 4 && pb + 4 <= act) {   // fully active: vector path
            float xp[4][4];
#pragma unroll
            for (int g = 0; g < 4; g++) {
                float4 v = __ldcg((const float4*)&g_xpre[(tb + g * Hv + j) * Bv + pb]);
                xp[g][0] = v.x; xp[g][1] = v.y; xp[g][2] = v.z; xp[g][3] = v.w;
            }
            float4 c4 = __ldcg((const float4*)&g_cT[hi]);
            float cold[4] = {c4.x, c4.y, c4.z, c4.w};
            float hn[4], cn[4];
#pragma unroll
            for (int p = 0; p < 4; p++) {
                float iv = sigmoidf_(acc[p][0] + xp[0][p]);
                float fv = sigmoidf_(acc[p][1] + xp[1][p]);
                float gv = tanhf_   (acc[p][2] + xp[2][p]);
                float ov = sigmoidf_(acc[p][3] + xp[3][p]);
                cn[p] = fv * cold[p] + iv * gv;
                hn[p] = ov * tanhf_(cn[p]);
            }
            __stcg((float4*)&hout[hi], make_float4(hn[0], hn[1], hn[2], hn[3]));
            __stcg((float4*)&g_cT[hi], make_float4(cn[0], cn[1], cn[2], cn[3]));
        } else {                            // straddle / narrow: masked scalar
#pragma unroll
            for (int p = 0; p < PPT; p++) {
                const int pp = pb + p;
                if (pp >= act) continue;
                float gi = acc[p][0] + __ldcg(&g_xpre[(tb + 0 * Hv + j) * Bv + pp]);
                float gf = acc[p][1] + __ldcg(&g_xpre[(tb + 1 * Hv + j) * Bv + pp]);
                float gg = acc[p][2] + __ldcg(&g_xpre[(tb + 2 * Hv + j) * Bv + pp]);
                float go = acc[p][3] + __ldcg(&g_xpre[(tb + 3 * Hv + j) * Bv + pp]);
                float iv = sigmoidf_(gi);
                float fv = sigmoidf_(gf);
                float gv = tanhf_(gg);
                float ov = sigmoidf_(go);
                float cold = __ldcg(&g_cT[hi + p]);
                float cnew = fv * cold + iv * gv;
                float hnew = ov * tanhf_(cnew);
                __stcg(&g_cT[hi + p], cnew);
                __stcg(&hout[hi + p], hnew);
            }
        }
    }
    __syncthreads();   // protect hs reuse by next dynamic tile
}

__global__ __launch_bounds__(NTHR, 4) void lstm_kernel()
{
    __shared__ __align__(16) float  hs[2][15][64];   // 7.5 KB, dbl-buffered
    __shared__ float4 ws4[2400];                     // 37.5 KB, phase-resident Wh
    __shared__ int    s_tile;

    const int bid = blockIdx.x;
    const int tid = threadIdx.x;
    int wlast = 0;

#pragma unroll 1
    for (int t = 0; t < Tv; t++) {
        const int act = g_act[t];
        const int na  = (act + 63) >> 6;
        const float* hin  = g_hT[t & 1];
        float*       hout = g_hT[(t & 1) ^ 1];

        int w, njt, lw;
        if      (na >= 9) { w = 8; njt = 38;  lw = 3; }
        else if (na >= 5) { w = 4; njt = 75;  lw = 2; }
        else              { w = 2; njt = 150; lw = 1; }
        const int jt = bid % njt;
        const int j0 = jt * w;

        if (w != wlast) {    // phase change: (re)load this block's Wh slice
            __syncthreads();
            for (int idx = tid; idx < 300 * w; idx += NTHR) {
                int k   = idx >> lw;
                int jj  = idx & (w - 1);
                int col = j0 + jj;
                ws4[idx] = (col < Hv) ? g_whT[k * Hv + col]
                                      : make_float4(0.f, 0.f, 0.f, 0.f);
            }
            wlast = w;
            __syncthreads();
        }

        // dynamic p-tile grab: per-(t, jt) ticket counter (monotone, no reset)
        for (;;) {
            if (tid == 0) s_tile = atomicAdd(&g_ctr[t][jt], 1);
            __syncthreads();
            const int x = s_tile;
            if (x >= na) break;
            if (w == 8)
                step_tile_full<8>(hs, ws4, hin, hout, t, x * 64, j0, act);
            else if (w == 4)
                step_tile_full<4>(hs, ws4, hin, hout, t, x * 64, j0, act);
            else
                step_tile_full<2>(hs, ws4, hin, hout, t, x * 64, j0, act);
        }
        grid_barrier(t + 1);
    }
}

// ---------------------------------------------------------------------------
// Output: final h for batch b lives in buffer lens[b] & 1 (written at len-1).
// ---------------------------------------------------------------------------
__global__ void out_kernel(const int* __restrict__ lens,
                           const float* __restrict__ Wout,
                           const float* __restrict__ bout,
                           float* __restrict__ out)
{
    int gwarp = (blockIdx.x * blockDim.x + threadIdx.x) >> 5;
    int lane  = threadIdx.x & 31;
    if (gwarp >= Bv) return;

    const int p = g_rank[gwarp];
    const float* hbuf = g_hT[lens[gwarp] & 1];
    float s0 = 0.f, s1 = 0.f, s2 = 0.f;
    for (int jj = lane; jj < Hv; jj += 32) {
        float hv = hbuf[jj * Bv + p];
        s0 = fmaf(hv, Wout[jj * 3 + 0], s0);
        s1 = fmaf(hv, Wout[jj * 3 + 1], s1);
        s2 = fmaf(hv, Wout[jj * 3 + 2], s2);
    }
#pragma unroll
    for (int off = 16; off > 0; off >>= 1) {
        s0 += __shfl_down_sync(0xffffffffu, s0, off);
        s1 += __shfl_down_sync(0xffffffffu, s1, off);
        s2 += __shfl_down_sync(0xffffffffu, s2, off);
    }
    if (lane == 0) {
        out[gwarp * 3 + 0] = s0 + bout[0];
        out[gwarp * 3 + 1] = s1 + bout[1];
        out[gwarp * 3 + 2] = s2 + bout[2];
    }
}

// ---------------------------------------------------------------------------
extern "C" void kernel_launch(void* const* d_in, const int* in_sizes, int n_in,
                              void* d_out, int out_size)
{
    const int*   sent = (const int*)  d_in[0];
    const int*   lens = (const int*)  d_in[1];
    const float* emb  = (const float*)d_in[2];
    const float* Wx   = (const float*)d_in[3];
    const float* Wh   = (const float*)d_in[4];
    const float* bias = (const float*)d_in[5];
    const float* Wout = (const float*)d_in[6];
    const float* bout = (const float*)d_in[7];
    float* out = (float*)d_out;

    init_kernel<<<1, 1024>>>(lens);
    zero_kernel<<<(Hv * Bv + 255) / 256, 256>>>();
    trans_kernel<<<(Hv * Hv + 255) / 256, 256>>>(Wh);

    dim3 pg(Bv / 128, (G4 + 127) / 128, Tv);   // 8 x 10 x 80
    pre_kernel<<<pg, 256>>>(sent, emb, Wx, bias);

    // one persistent launch for all 80 timesteps
    lstm_kernel<<<NBLK, NTHR>>>();

    out_kernel<<<(Bv * 32 + 127) / 128, 128>>>(lens, Wout, bout, out);
}

// round 8
// speedup vs baseline: 1.0322x; 1.0322x over previous
#include <cuda_runtime.h>

// Problem dims (fixed by setup_inputs)
#define Bv   1024
#define Tv   80
#define Dv   300
#define Hv   300
#define G4   1200           // 4*H
#define NBLK 570            // 15 p-groups x 38 j-tiles; 4/SM co-resident
#define NTHR 256

// Scratch (device globals — no allocation allowed)
__device__ float g_xpre[(size_t)Tv * G4 * Bv];   // xpre[t][n][p]
__device__ float g_hT[2][Hv * Bv];               // hT[k][p], double buffered
__device__ float g_cT[Hv * Bv];                  // cT[j][p]
__device__ float4 g_whT[Hv * Hv];                // whT[k*H+j] = 4 gate weights
__device__ int   g_perm[Bv];
__device__ int   g_rank[Bv];
__device__ int   g_act[Tv];
__device__ unsigned g_bar_count;
__device__ unsigned g_bar_sense;

// ---------------------------------------------------------------------------
__global__ void init_kernel(const int* __restrict__ lens) {
    __shared__ int sl[Bv];
    const int tid = threadIdx.x;
    sl[tid] = lens[tid];
    __syncthreads();
    const int L = sl[tid];
    int r = 0;
    for (int b = 0; b < Bv; b++) {
        int L2 = sl[b];
        r += (L2 > L) || (L2 == L && b < tid);
    }
    g_rank[tid] = r;
    g_perm[r]   = tid;
    if (tid < Tv) {
        int c = 0;
        for (int b = 0; b < Bv; b++) c += (sl[b] > tid);
        g_act[tid] = c;
    }
    if (tid == 0) { g_bar_count = 0; g_bar_sense = 0; }
}

__global__ void zero_kernel() {
    int i = blockIdx.x * blockDim.x + threadIdx.x;
    if (i < Hv * Bv) {
        g_hT[0][i] = 0.f;
        g_hT[1][i] = 0.f;
        g_cT[i]    = 0.f;
    }
}

// Transpose Wh[k][g*H+j] -> whT[k*H+j] = float4(g0,g1,g2,g3)
__global__ void trans_kernel(const float* __restrict__ Wh) {
    int i = blockIdx.x * blockDim.x + threadIdx.x;
    if (i < Hv * Hv) {
        int k = i / Hv, j = i - k * Hv;
        const float* r = Wh + k * G4 + j;
        g_whT[i] = make_float4(r[0], r[Hv], r[2 * Hv], r[3 * Hv]);
    }
}

// ---------------------------------------------------------------------------
// Precompute xpre[t][n][p]
// ---------------------------------------------------------------------------
__global__ __launch_bounds__(256, 2) void pre_kernel(
    const int*   __restrict__ sent,
    const float* __restrict__ emb,
    const float* __restrict__ Wx,
    const float* __restrict__ bias)
{
    const int t  = blockIdx.z;
    const int p0 = blockIdx.x * 128;
    const int n0 = blockIdx.y * 128;
    if (p0 >= g_act[t]) return;

    __shared__ int   idxs[128];
    __shared__ __align__(16) float es[20][128];
    __shared__ __align__(16) float ws[20][128];

    const int tid = threadIdx.x;
    const int tx  = tid & 15;
    const int ty  = tid >> 4;

    if (tid < 128) idxs[tid] = sent[g_perm[p0 + tid] * Tv + t];
    __syncthreads();

    float acc[8][8];
#pragma unroll
    for (int i = 0; i < 8; i++)
#pragma unroll
        for (int j = 0; j < 8; j++) acc[i][j] = 0.f;

    for (int k0 = 0; k0 < Dv; k0 += 20) {
#pragma unroll
        for (int r = 0; r < 10; r++) {
            int f  = r * 256 + tid;
            int rl = f & 127;
            int kl = f >> 7;
            es[kl][rl] = emb[(size_t)idxs[rl] * Dv + k0 + kl];
            int n = n0 + rl;
            ws[kl][rl] = (n < G4) ? Wx[(k0 + kl) * G4 + n] : 0.f;
        }
        __syncthreads();
#pragma unroll
        for (int k = 0; k < 20; k++) {
            float4 a0 = *(const float4*)&es[k][tx * 4];
            float4 a1 = *(const float4*)&es[k][tx * 4 + 64];
            float4 w0 = *(const float4*)&ws[k][ty * 4];
            float4 w1 = *(const float4*)&ws[k][ty * 4 + 64];
            float a[8] = {a0.x, a0.y, a0.z, a0.w, a1.x, a1.y, a1.z, a1.w};
            float w[8] = {w0.x, w0.y, w0.z, w0.w, w1.x, w1.y, w1.z, w1.w};
#pragma unroll
            for (int ni = 0; ni < 8; ni++)
#pragma unroll
                for (int pi = 0; pi < 8; pi++)
                    acc[ni][pi] = fmaf(w[ni], a[pi], acc[ni][pi]);
        }
        __syncthreads();
    }

#pragma unroll
    for (int ni = 0; ni < 8; ni++) {
        int n = n0 + (ni >> 2) * 64 + ty * 4 + (ni & 3);
        if (n >= G4) continue;
        float bn = bias[n];
        size_t base = ((size_t)t * G4 + n) * Bv + p0;
        float4 v0 = make_float4(acc[ni][0] + bn, acc[ni][1] + bn,
                                acc[ni][2] + bn, acc[ni][3] + bn);
        float4 v1 = make_float4(acc[ni][4] + bn, acc[ni][5] + bn,
                                acc[ni][6] + bn, acc[ni][7] + bn);
        *(float4*)&g_xpre[base + tx * 4]      = v0;
        *(float4*)&g_xpre[base + tx * 4 + 64] = v1;
    }
}

// ---------------------------------------------------------------------------
// Persistent LSTM recurrence: Wh phase-resident in smem, static p striding,
// 256-thread blocks (8 warps/SMSP) for issue-slot coverage.
// ---------------------------------------------------------------------------
__device__ __forceinline__ float sigmoidf_(float x) {
    return 1.f / (1.f + __expf(-x));
}
__device__ __forceinline__ float tanhf_(float x) {
    return 1.f - 2.f / (__expf(2.f * x) + 1.f);
}

__device__ __forceinline__ void grid_barrier(unsigned target) {
    __threadfence();
    __syncthreads();
    if (threadIdx.x == 0) {
        if (atomicAdd(&g_bar_count, 1u) == NBLK - 1) {
            g_bar_count = 0;
            __threadfence();
            atomicExch(&g_bar_sense, target);
        } else {
            while (*(volatile unsigned*)&g_bar_sense < target) __nanosleep(32);
        }
    }
    __syncthreads();
}

// One tile: 64 p x W j-cols x 4 gates, 256 threads (W=8: PPT=2; W=4: PPT=1).
// Wh resident in ws4. h staged per 15-k chunk (double-buffered, 1 sync/chunk).
template<int W>
__device__ __forceinline__ void step_tile_full(
    float hs[2][15][64], const float4* __restrict__ ws4,
    const float* __restrict__ hin, float* __restrict__ hout,
    int t, int p0, int j0, int act)
{
    constexpr int TPJ = NTHR / W;        // 32 or 64
    constexpr int PPT = 64 / TPJ;        // 2 or 1
    const int tid  = threadIdx.x;
    const int pidx = tid % TPJ;
    const int jc   = tid / TPJ;
    const int j    = j0 + jc;
    const bool ldon = tid < 240;         // 240 float4 = 15k x 64p per chunk

    float4 ph;
    auto load_c = [&](int k0) {
        if (ldon)
            ph = __ldcg((const float4*)&hin[(k0 + (tid >> 4)) * Bv + p0
                                            + ((tid & 15) << 2)]);
    };
    auto store_c = [&](int buf) {
        if (ldon)
            *(float4*)&hs[buf][tid >> 4][(tid & 15) << 2] = ph;
    };

    float acc[PPT][4];
#pragma unroll
    for (int p = 0; p < PPT; p++)
#pragma unroll
        for (int g = 0; g < 4; g++) acc[p][g] = 0.f;

    load_c(0);
    store_c(0);
    __syncthreads();

#pragma unroll 1
    for (int c = 0; c < 20; c++) {
        const int cur = c & 1;
        if (c < 19) load_c((c + 1) * 15);
#pragma unroll
        for (int kk = 0; kk < 15; kk++) {
            const int k = c * 15 + kk;
            float4 w4 = ws4[k * W + jc];
            if (PPT == 2) {
                float2 h2 = *(const float2*)&hs[cur][kk][pidx * 2];
                acc[0][0] = fmaf(h2.x, w4.x, acc[0][0]);
                acc[0][1] = fmaf(h2.x, w4.y, acc[0][1]);
                acc[0][2] = fmaf(h2.x, w4.z, acc[0][2]);
                acc[0][3] = fmaf(h2.x, w4.w, acc[0][3]);
                acc[1][0] = fmaf(h2.y, w4.x, acc[1][0]);
                acc[1][1] = fmaf(h2.y, w4.y, acc[1][1]);
                acc[1][2] = fmaf(h2.y, w4.z, acc[1][2]);
                acc[1][3] = fmaf(h2.y, w4.w, acc[1][3]);
            } else {
                float hv = hs[cur][kk][pidx];
                acc[0][0] = fmaf(hv, w4.x, acc[0][0]);
                acc[0][1] = fmaf(hv, w4.y, acc[0][1]);
                acc[0][2] = fmaf(hv, w4.z, acc[0][2]);
                acc[0][3] = fmaf(hv, w4.w, acc[0][3]);
            }
        }
        if (c < 19) { store_c(cur ^ 1); __syncthreads(); }
    }

    if (j >= Hv) return;

    const size_t tb = (size_t)t * G4;
    const int pb = p0 + pidx * PPT;
    const int hi = j * Bv + pb;

    if (PPT == 2 && pb + 2 <= act) {       // fully active: float2 path
        float xp[4][2];
#pragma unroll
        for (int g = 0; g < 4; g++) {
            float2 v = __ldcg((const float2*)&g_xpre[(tb + g * Hv + j) * Bv + pb]);
            xp[g][0] = v.x; xp[g][1] = v.y;
        }
        float2 c2 = __ldcg((const float2*)&g_cT[hi]);
        float cold[2] = {c2.x, c2.y};
        float hn[2], cn[2];
#pragma unroll
        for (int p = 0; p < 2; p++) {
            float iv = sigmoidf_(acc[p][0] + xp[0][p]);
            float fv = sigmoidf_(acc[p][1] + xp[1][p]);
            float gv = tanhf_   (acc[p][2] + xp[2][p]);
            float ov = sigmoidf_(acc[p][3] + xp[3][p]);
            cn[p] = fv * cold[p] + iv * gv;
            hn[p] = ov * tanhf_(cn[p]);
        }
        __stcg((float2*)&hout[hi], make_float2(hn[0], hn[1]));
        __stcg((float2*)&g_cT[hi], make_float2(cn[0], cn[1]));
    } else {                                // straddle / narrow: masked scalar
#pragma unroll
        for (int p = 0; p < PPT; p++) {
            const int pp = pb + p;
            if (pp >= act) continue;
            float gi = acc[p][0] + __ldcg(&g_xpre[(tb + 0 * Hv + j) * Bv + pp]);
            float gf = acc[p][1] + __ldcg(&g_xpre[(tb + 1 * Hv + j) * Bv + pp]);
            float gg = acc[p][2] + __ldcg(&g_xpre[(tb + 2 * Hv + j) * Bv + pp]);
            float go = acc[p][3] + __ldcg(&g_xpre[(tb + 3 * Hv + j) * Bv + pp]);
            float iv = sigmoidf_(gi);
            float fv = sigmoidf_(gf);
            float gv = tanhf_(gg);
            float ov = sigmoidf_(go);
            float cold = __ldcg(&g_cT[hi + p]);
            float cnew = fv * cold + iv * gv;
            float hnew = ov * tanhf_(cnew);
            __stcg(&g_cT[hi + p], cnew);
            __stcg(&hout[hi + p], hnew);
        }
    }
}

__global__ __launch_bounds__(NTHR, 4) void lstm_kernel()
{
    __shared__ __align__(16) float  hs[2][15][64];   // 7.5 KB, dbl-buffered
    __shared__ float4 ws4[2400];                     // 37.5 KB, phase-resident Wh

    const int bid = blockIdx.x;
    const int tid = threadIdx.x;
    int wlast = 0;

#pragma unroll 1
    for (int t = 0; t < Tv; t++) {
        const int act = g_act[t];
        const int na  = (act + 63) >> 6;
        const float* hin  = g_hT[t & 1];
        float*       hout = g_hT[(t & 1) ^ 1];

        int w, njt, lw;
        if (na >= 9) { w = 8; njt = 38; lw = 3; }
        else         { w = 4; njt = 75; lw = 2; }
        const int jt  = bid % njt;
        const int ptb = bid / njt;
        const int j0  = jt * w;

        if (w != wlast) {    // phase change: (re)load this block's Wh slice
            for (int idx = tid; idx < 300 * w; idx += NTHR) {
                int k   = idx >> lw;
                int jj  = idx & (w - 1);
                int col = j0 + jj;
                ws4[idx] = (col < Hv) ? g_whT[k * Hv + col]
                                      : make_float4(0.f, 0.f, 0.f, 0.f);
            }
            wlast = w;
            __syncthreads();
        }

        int stride;
        if (w == 8) stride = 15;                    // 570 = 15*38 exact
        else        stride = (jt < 45) ? 8 : 7;     // 570 = 7*75 + 45

        if (w == 8) {
            for (int pp = ptb; pp * 64 < act; pp += stride)
                step_tile_full<8>(hs, ws4, hin, hout, t, pp * 64, j0, act);
        } else {
            for (int pp = ptb; pp * 64 < act; pp += stride)
                step_tile_full<4>(hs, ws4, hin, hout, t, pp * 64, j0, act);
        }
        grid_barrier(t + 1);
    }
}

// ---------------------------------------------------------------------------
// Output: final h for batch b lives in buffer lens[b] & 1 (written at len-1).
// ---------------------------------------------------------------------------
__global__ void out_kernel(const int* __restrict__ lens,
                           const float* __restrict__ Wout,
                           const float* __restrict__ bout,
                           float* __restrict__ out)
{
    int gwarp = (blockIdx.x * blockDim.x + threadIdx.x) >> 5;
    int lane  = threadIdx.x & 31;
    if (gwarp >= Bv) return;

    const int p = g_rank[gwarp];
    const float* hbuf = g_hT[lens[gwarp] & 1];
    float s0 = 0.f, s1 = 0.f, s2 = 0.f;
    for (int jj = lane; jj < Hv; jj += 32) {
        float hv = hbuf[jj * Bv + p];
        s0 = fmaf(hv, Wout[jj * 3 + 0], s0);
        s1 = fmaf(hv, Wout[jj * 3 + 1], s1);
        s2 = fmaf(hv, Wout[jj * 3 + 2], s2);
    }
#pragma unroll
    for (int off = 16; off > 0; off >>= 1) {
        s0 += __shfl_down_sync(0xffffffffu, s0, off);
        s1 += __shfl_down_sync(0xffffffffu, s1, off);
        s2 += __shfl_down_sync(0xffffffffu, s2, off);
    }
    if (lane == 0) {
        out[gwarp * 3 + 0] = s0 + bout[0];
        out[gwarp * 3 + 1] = s1 + bout[1];
        out[gwarp * 3 + 2] = s2 + bout[2];
    }
}

// ---------------------------------------------------------------------------
extern "C" void kernel_launch(void* const* d_in, const int* in_sizes, int n_in,
                              void* d_out, int out_size)
{
    const int*   sent = (const int*)  d_in[0];
    const int*   lens = (const int*)  d_in[1];
    const float* emb  = (const float*)d_in[2];
    const float* Wx   = (const float*)d_in[3];
    const float* Wh   = (const float*)d_in[4];
    const float* bias = (const float*)d_in[5];
    const float* Wout = (const float*)d_in[6];
    const float* bout = (const float*)d_in[7];
    float* out = (float*)d_out;

    init_kernel<<<1, 1024>>>(lens);
    zero_kernel<<<(Hv * Bv + 255) / 256, 256>>>();
    trans_kernel<<<(Hv * Hv + 255) / 256, 256>>>(Wh);

    dim3 pg(Bv / 128, (G4 + 127) / 128, Tv);   // 8 x 10 x 80
    pre_kernel<<<pg, 256>>>(sent, emb, Wx, bias);

    // one persistent launch for all 80 timesteps
    lstm_kernel<<<NBLK, NTHR>>>();

    out_kernel<<<(Bv * 32 + 127) / 128, 128>>>(lens, Wout, bout, out);
}

// round 9
// speedup vs baseline: 1.1177x; 1.0828x over previous
#include <cuda_runtime.h>

// Problem dims (fixed by setup_inputs)
#define Bv   1024
#define Tv   80
#define Dv   300
#define Hv   300
#define G4   1200           // 4*H
#define NBLK 285            // 19 j-tiles x 15 p-strides; 2/SM resident (90KB smem)
#define NTHR 512
#define LSTM_SMEM (76800 + 15360)   // ws4 (300*16 float4) + hs (2*30*64 f32)

// Scratch (device globals — no allocation allowed)
__device__ float g_xpre[(size_t)Tv * G4 * Bv];   // xpre[t][n][p]
__device__ float g_hT[2][Hv * Bv];               // hT[k][p], double buffered
__device__ float g_cT[Hv * Bv];                  // cT[j][p]
__device__ float4 g_whT[Hv * Hv];                // whT[k*H+j] = 4 gate weights
__device__ int   g_perm[Bv];
__device__ int   g_rank[Bv];
__device__ int   g_act[Tv];
__device__ unsigned g_bar_count;
__device__ unsigned g_bar_sense;

// ---------------------------------------------------------------------------
__global__ void init_kernel(const int* __restrict__ lens) {
    __shared__ int sl[Bv];
    const int tid = threadIdx.x;
    sl[tid] = lens[tid];
    __syncthreads();
    const int L = sl[tid];
    int r = 0;
    for (int b = 0; b < Bv; b++) {
        int L2 = sl[b];
        r += (L2 > L) || (L2 == L && b < tid);
    }
    g_rank[tid] = r;
    g_perm[r]   = tid;
    if (tid < Tv) {
        int c = 0;
        for (int b = 0; b < Bv; b++) c += (sl[b] > tid);
        g_act[tid] = c;
    }
    if (tid == 0) { g_bar_count = 0; g_bar_sense = 0; }
}

__global__ void zero_kernel() {
    int i = blockIdx.x * blockDim.x + threadIdx.x;
    if (i < Hv * Bv) {
        g_hT[0][i] = 0.f;
        g_hT[1][i] = 0.f;
        g_cT[i]    = 0.f;
    }
}

// Transpose Wh[k][g*H+j] -> whT[k*H+j] = float4(g0,g1,g2,g3)
__global__ void trans_kernel(const float* __restrict__ Wh) {
    int i = blockIdx.x * blockDim.x + threadIdx.x;
    if (i < Hv * Hv) {
        int k = i / Hv, j = i - k * Hv;
        const float* r = Wh + k * G4 + j;
        g_whT[i] = make_float4(r[0], r[Hv], r[2 * Hv], r[3 * Hv]);
    }
}

// ---------------------------------------------------------------------------
// Precompute xpre[t][n][p] — float4 staging everywhere.
// ---------------------------------------------------------------------------
__global__ __launch_bounds__(256, 2) void pre_kernel(
    const int*   __restrict__ sent,
    const float* __restrict__ emb,
    const float* __restrict__ Wx,
    const float* __restrict__ bias)
{
    const int t  = blockIdx.z;
    const int p0 = blockIdx.x * 128;
    const int n0 = blockIdx.y * 128;
    if (p0 >= g_act[t]) return;

    __shared__ int   idxs[128];
    __shared__ __align__(16) float es[20][128];
    __shared__ __align__(16) float ws[20][128];

    const int tid = threadIdx.x;
    const int tx  = tid & 15;
    const int ty  = tid >> 4;

    if (tid < 128) idxs[tid] = sent[g_perm[p0 + tid] * Tv + t];
    __syncthreads();

    float acc[8][8];
#pragma unroll
    for (int i = 0; i < 8; i++)
#pragma unroll
        for (int j = 0; j < 8; j++) acc[i][j] = 0.f;

    for (int k0 = 0; k0 < Dv; k0 += 20) {
        // ws: 640 float4, coalesced LDG.128 -> STS.128
#pragma unroll
        for (int i = 0; i < 3; i++) {
            int idx = i * 256 + tid;
            if (idx < 640) {
                int kl = idx >> 5;
                int nq = idx & 31;
                int n  = n0 + nq * 4;
                float4 v = (n < G4) ? *(const float4*)&Wx[(k0 + kl) * G4 + n]
                                    : make_float4(0.f, 0.f, 0.f, 0.f);
                *(float4*)&ws[kl][nq * 4] = v;
            }
        }
        // es: 640 float4 along k (16B gather), conflict-free transposing STS
#pragma unroll
        for (int i = 0; i < 3; i++) {
            int idx = i * 256 + tid;
            if (idx < 640) {
                int ks = idx >> 7;          // 0..4 (warp-uniform)
                int rl = idx & 127;
                float4 v = *(const float4*)&emb[(size_t)idxs[rl] * Dv + k0 + ks * 4];
                es[ks * 4 + 0][rl] = v.x;
                es[ks * 4 + 1][rl] = v.y;
                es[ks * 4 + 2][rl] = v.z;
                es[ks * 4 + 3][rl] = v.w;
            }
        }
        __syncthreads();
#pragma unroll
        for (int k = 0; k < 20; k++) {
            float4 a0 = *(const float4*)&es[k][tx * 4];
            float4 a1 = *(const float4*)&es[k][tx * 4 + 64];
            float4 w0 = *(const float4*)&ws[k][ty * 4];
            float4 w1 = *(const float4*)&ws[k][ty * 4 + 64];
            float a[8] = {a0.x, a0.y, a0.z, a0.w, a1.x, a1.y, a1.z, a1.w};
            float w[8] = {w0.x, w0.y, w0.z, w0.w, w1.x, w1.y, w1.z, w1.w};
#pragma unroll
            for (int ni = 0; ni < 8; ni++)
#pragma unroll
                for (int pi = 0; pi < 8; pi++)
                    acc[ni][pi] = fmaf(w[ni], a[pi], acc[ni][pi]);
        }
        __syncthreads();
    }

#pragma unroll
    for (int ni = 0; ni < 8; ni++) {
        int n = n0 + (ni >> 2) * 64 + ty * 4 + (ni & 3);
        if (n >= G4) continue;
        float bn = bias[n];
        size_t base = ((size_t)t * G4 + n) * Bv + p0;
        float4 v0 = make_float4(acc[ni][0] + bn, acc[ni][1] + bn,
                                acc[ni][2] + bn, acc[ni][3] + bn);
        float4 v1 = make_float4(acc[ni][4] + bn, acc[ni][5] + bn,
                                acc[ni][6] + bn, acc[ni][7] + bn);
        __stcs((float4*)&g_xpre[base + tx * 4],      v0);
        __stcs((float4*)&g_xpre[base + tx * 4 + 64], v1);
    }
}

// ---------------------------------------------------------------------------
// Persistent LSTM recurrence: Wh phase-resident (one reload total), 512 thr,
// W=16 j-tiles (halved h L2 traffic), chunk=30k (10 syncs/tile).
// ---------------------------------------------------------------------------
__device__ __forceinline__ float sigmoidf_(float x) {
    return 1.f / (1.f + __expf(-x));
}
__device__ __forceinline__ float tanhf_(float x) {
    return 1.f - 2.f / (__expf(2.f * x) + 1.f);
}

__device__ __forceinline__ void grid_barrier(unsigned target) {
    __threadfence();
    __syncthreads();
    if (threadIdx.x == 0) {
        if (atomicAdd(&g_bar_count, 1u) == NBLK - 1) {
            g_bar_count = 0;
            __threadfence();
            atomicExch(&g_bar_sense, target);
        } else {
            while (*(volatile unsigned*)&g_bar_sense < target) __nanosleep(32);
        }
    }
    __syncthreads();
}

// One tile: 64 p x W j-cols x 4 gates, 512 threads (W=16: PPT=2; W=8: PPT=1).
template<int W>
__device__ __forceinline__ void step_tile_full(
    float hs[2][30][64], const float4* __restrict__ ws4,
    const float* __restrict__ hin, float* __restrict__ hout,
    int t, int p0, int j0, int act)
{
    constexpr int TPJ = NTHR / W;        // 32 or 64
    constexpr int PPT = 64 / TPJ;        // 2 or 1
    const int tid  = threadIdx.x;
    const int pidx = tid % TPJ;
    const int jc   = tid / TPJ;
    const int j    = j0 + jc;
    const bool ldon = tid < 480;         // 480 float4 = 30k x 64p per chunk

    float4 ph;
    auto load_c = [&](int k0) {
        if (ldon)
            ph = __ldcg((const float4*)&hin[(k0 + (tid >> 4)) * Bv + p0
                                            + ((tid & 15) << 2)]);
    };
    auto store_c = [&](int buf) {
        if (ldon)
            *(float4*)&hs[buf][tid >> 4][(tid & 15) << 2] = ph;
    };

    float acc[PPT][4];
#pragma unroll
    for (int p = 0; p < PPT; p++)
#pragma unroll
        for (int g = 0; g < 4; g++) acc[p][g] = 0.f;

    load_c(0);
    store_c(0);
    __syncthreads();

#pragma unroll 1
    for (int c = 0; c < 10; c++) {
        const int cur = c & 1;
        if (c < 9) load_c((c + 1) * 30);
#pragma unroll
        for (int kk = 0; kk < 30; kk++) {
            const int k = c * 30 + kk;
            float4 w4 = ws4[k * W + jc];
            if (PPT == 2) {
                float2 h2 = *(const float2*)&hs[cur][kk][pidx * 2];
                acc[0][0] = fmaf(h2.x, w4.x, acc[0][0]);
                acc[0][1] = fmaf(h2.x, w4.y, acc[0][1]);
                acc[0][2] = fmaf(h2.x, w4.z, acc[0][2]);
                acc[0][3] = fmaf(h2.x, w4.w, acc[0][3]);
                acc[1][0] = fmaf(h2.y, w4.x, acc[1][0]);
                acc[1][1] = fmaf(h2.y, w4.y, acc[1][1]);
                acc[1][2] = fmaf(h2.y, w4.z, acc[1][2]);
                acc[1][3] = fmaf(h2.y, w4.w, acc[1][3]);
            } else {
                float hv = hs[cur][kk][pidx];
                acc[0][0] = fmaf(hv, w4.x, acc[0][0]);
                acc[0][1] = fmaf(hv, w4.y, acc[0][1]);
                acc[0][2] = fmaf(hv, w4.z, acc[0][2]);
                acc[0][3] = fmaf(hv, w4.w, acc[0][3]);
            }
        }
        if (c < 9) { store_c(cur ^ 1); __syncthreads(); }
    }

    if (j < Hv) {
        const size_t tb = (size_t)t * G4;
        const int pb = p0 + pidx * PPT;
        const int hi = j * Bv + pb;

        if (PPT == 2 && pb + 2 <= act) {   // fully active: float2 path
            float xp[4][2];
#pragma unroll
            for (int g = 0; g < 4; g++) {
                float2 v = __ldcs((const float2*)&g_xpre[(tb + g * Hv + j) * Bv + pb]);
                xp[g][0] = v.x; xp[g][1] = v.y;
            }
            float2 c2 = __ldcg((const float2*)&g_cT[hi]);
            float cold[2] = {c2.x, c2.y};
            float hn[2], cn[2];
#pragma unroll
            for (int p = 0; p < 2; p++) {
                float iv = sigmoidf_(acc[p][0] + xp[0][p]);
                float fv = sigmoidf_(acc[p][1] + xp[1][p]);
                float gv = tanhf_   (acc[p][2] + xp[2][p]);
                float ov = sigmoidf_(acc[p][3] + xp[3][p]);
                cn[p] = fv * cold[p] + iv * gv;
                hn[p] = ov * tanhf_(cn[p]);
            }
            __stcg((float2*)&hout[hi], make_float2(hn[0], hn[1]));
            __stcg((float2*)&g_cT[hi], make_float2(cn[0], cn[1]));
        } else {                            // straddle / narrow: masked scalar
#pragma unroll
            for (int p = 0; p < PPT; p++) {
                const int pp = pb + p;
                if (pp >= act) continue;
                float gi = acc[p][0] + __ldcs(&g_xpre[(tb + 0 * Hv + j) * Bv + pp]);
                float gf = acc[p][1] + __ldcs(&g_xpre[(tb + 1 * Hv + j) * Bv + pp]);
                float gg = acc[p][2] + __ldcs(&g_xpre[(tb + 2 * Hv + j) * Bv + pp]);
                float go = acc[p][3] + __ldcs(&g_xpre[(tb + 3 * Hv + j) * Bv + pp]);
                float iv = sigmoidf_(gi);
                float fv = sigmoidf_(gf);
                float gv = tanhf_(gg);
                float ov = sigmoidf_(go);
                float cold = __ldcg(&g_cT[hi + p]);
                float cnew = fv * cold + iv * gv;
                float hnew = ov * tanhf_(cnew);
                __stcg(&g_cT[hi + p], cnew);
                __stcg(&hout[hi + p], hnew);
            }
        }
    }
    __syncthreads();   // protect hs before next tile reuses it
}

__global__ __launch_bounds__(NTHR, 2) void lstm_kernel()
{
    extern __shared__ __align__(16) char smem_raw[];
    float4* ws4 = (float4*)smem_raw;                          // 76800 B
    float (*hs)[30][64] = (float(*)[30][64])(smem_raw + 76800); // 15360 B

    const int bid = blockIdx.x;
    const int tid = threadIdx.x;
    int wlast = 0;

#pragma unroll 1
    for (int t = 0; t < Tv; t++) {
        const int act = g_act[t];
        const int na  = (act + 63) >> 6;
        const float* hin  = g_hT[t & 1];
        float*       hout = g_hT[(t & 1) ^ 1];

        int w, njt, lw;
        if (na >= 8) { w = 16; njt = 19; lw = 4; }
        else         { w = 8;  njt = 38; lw = 3; }
        const int jt  = bid % njt;
        const int ptb = bid / njt;
        const int j0  = jt * w;

        if (w != wlast) {    // phase change (happens once): load Wh slice
            for (int idx = tid; idx < 300 * w; idx += NTHR) {
                int k   = idx >> lw;
                int jj  = idx & (w - 1);
                int col = j0 + jj;
                ws4[idx] = (col < Hv) ? g_whT[k * Hv + col]
                                      : make_float4(0.f, 0.f, 0.f, 0.f);
            }
            wlast = w;
            __syncthreads();
        }

        int stride;
        if (w == 16) stride = 15;                   // 285 = 19*15 exact
        else         stride = (jt < 19) ? 8 : 7;    // 285 = 7*38 + 19

        if (w == 16) {
            for (int pp = ptb; pp * 64 < act; pp += stride)
                step_tile_full<16>(hs, ws4, hin, hout, t, pp * 64, j0, act);
        } else {
            for (int pp = ptb; pp * 64 < act; pp += stride)
                step_tile_full<8>(hs, ws4, hin, hout, t, pp * 64, j0, act);
        }
        grid_barrier(t + 1);
    }
}

// ---------------------------------------------------------------------------
// Output: final h for batch b lives in buffer lens[b] & 1 (written at len-1).
// ---------------------------------------------------------------------------
__global__ void out_kernel(const int* __restrict__ lens,
                           const float* __restrict__ Wout,
                           const float* __restrict__ bout,
                           float* __restrict__ out)
{
    int gwarp = (blockIdx.x * blockDim.x + threadIdx.x) >> 5;
    int lane  = threadIdx.x & 31;
    if (gwarp >= Bv) return;

    const int p = g_rank[gwarp];
    const float* hbuf = g_hT[lens[gwarp] & 1];
    float s0 = 0.f, s1 = 0.f, s2 = 0.f;
    for (int jj = lane; jj < Hv; jj += 32) {
        float hv = hbuf[jj * Bv + p];
        s0 = fmaf(hv, Wout[jj * 3 + 0], s0);
        s1 = fmaf(hv, Wout[jj * 3 + 1], s1);
        s2 = fmaf(hv, Wout[jj * 3 + 2], s2);
    }
#pragma unroll
    for (int off = 16; off > 0; off >>= 1) {
        s0 += __shfl_down_sync(0xffffffffu, s0, off);
        s1 += __shfl_down_sync(0xffffffffu, s1, off);
        s2 += __shfl_down_sync(0xffffffffu, s2, off);
    }
    if (lane == 0) {
        out[gwarp * 3 + 0] = s0 + bout[0];
        out[gwarp * 3 + 1] = s1 + bout[1];
        out[gwarp * 3 + 2] = s2 + bout[2];
    }
}

// ---------------------------------------------------------------------------
extern "C" void kernel_launch(void* const* d_in, const int* in_sizes, int n_in,
                              void* d_out, int out_size)
{
    const int*   sent = (const int*)  d_in[0];
    const int*   lens = (const int*)  d_in[1];
    const float* emb  = (const float*)d_in[2];
    const float* Wx   = (const float*)d_in[3];
    const float* Wh   = (const float*)d_in[4];
    const float* bias = (const float*)d_in[5];
    const float* Wout = (const float*)d_in[6];
    const float* bout = (const float*)d_in[7];
    float* out = (float*)d_out;

    cudaFuncSetAttribute(lstm_kernel,
                         cudaFuncAttributeMaxDynamicSharedMemorySize, LSTM_SMEM);

    init_kernel<<<1, 1024>>>(lens);
    zero_kernel<<<(Hv * Bv + 255) / 256, 256>>>();
    trans_kernel<<<(Hv * Hv + 255) / 256, 256>>>(Wh);

    dim3 pg(Bv / 128, (G4 + 127) / 128, Tv);   // 8 x 10 x 80
    pre_kernel<<<pg, 256>>>(sent, emb, Wx, bias);

    // one persistent launch for all 80 timesteps
    lstm_kernel<<<NBLK, NTHR, LSTM_SMEM>>>();

    out_kernel<<<(Bv * 32 + 127) / 128, 128>>>(lens, Wout, bout, out);
}

// round 10
// speedup vs baseline: 1.1248x; 1.0064x over previous
#include <cuda_runtime.h>

// Problem dims (fixed by setup_inputs)
#define Bv   1024
#define Tv   80
#define Dv   300
#define Hv   300
#define G4   1200           // 4*H
#define NBLK 285            // 19 j-tiles x 15 p-strides; 2/SM resident (90KB smem)
#define NTHR 512
#define LSTM_SMEM (76800 + 15360)   // ws4 (300*16 float4) + hs (2*30*64 f32)

typedef unsigned long long ull;

// ---- packed f32x2 helpers (Blackwell sm_100+) ------------------------------
__device__ __forceinline__ ull pack_dup(float x) {
    ull r; unsigned u = __float_as_uint(x);
    asm("mov.b64 %0, {%1, %1};" : "=l"(r) : "r"(u));
    return r;
}
__device__ __forceinline__ void fma2(ull& d, ull a, ull b) {
    asm("fma.rn.f32x2 %0, %1, %2, %0;" : "+l"(d) : "l"(a), "l"(b));
}
__device__ __forceinline__ float2 unpack2(ull v) {
    unsigned lo, hi;
    asm("mov.b64 {%0, %1}, %2;" : "=r"(lo), "=r"(hi) : "l"(v));
    return make_float2(__uint_as_float(lo), __uint_as_float(hi));
}

// Scratch (device globals — no allocation allowed)
__device__ float g_xpre[(size_t)Tv * G4 * Bv];   // xpre[t][n][p]
__device__ float g_hT[2][Hv * Bv];               // hT[k][p], double buffered
__device__ float g_cT[Hv * Bv];                  // cT[j][p]
__device__ float4 g_whT[Hv * Hv];                // whT[k*H+j] = 4 gate weights
__device__ int   g_perm[Bv];
__device__ int   g_rank[Bv];
__device__ int   g_act[Tv];
__device__ unsigned g_bar_count;
__device__ unsigned g_bar_sense;

// ---------------------------------------------------------------------------
__global__ void init_kernel(const int* __restrict__ lens) {
    __shared__ int sl[Bv];
    const int tid = threadIdx.x;
    sl[tid] = lens[tid];
    __syncthreads();
    const int L = sl[tid];
    int r = 0;
    for (int b = 0; b < Bv; b++) {
        int L2 = sl[b];
        r += (L2 > L) || (L2 == L && b < tid);
    }
    g_rank[tid] = r;
    g_perm[r]   = tid;
    if (tid < Tv) {
        int c = 0;
        for (int b = 0; b < Bv; b++) c += (sl[b] > tid);
        g_act[tid] = c;
    }
    if (tid == 0) { g_bar_count = 0; g_bar_sense = 0; }
}

__global__ void zero_kernel() {
    int i = blockIdx.x * blockDim.x + threadIdx.x;
    if (i < Hv * Bv) {
        g_hT[0][i] = 0.f;
        g_hT[1][i] = 0.f;
        g_cT[i]    = 0.f;
    }
}

// Transpose Wh[k][g*H+j] -> whT[k*H+j] = float4(g0,g1,g2,g3)
__global__ void trans_kernel(const float* __restrict__ Wh) {
    int i = blockIdx.x * blockDim.x + threadIdx.x;
    if (i < Hv * Hv) {
        int k = i / Hv, j = i - k * Hv;
        const float* r = Wh + k * G4 + j;
        g_whT[i] = make_float4(r[0], r[Hv], r[2 * Hv], r[3 * Hv]);
    }
}

// ---------------------------------------------------------------------------
// Precompute xpre[t][n][p] — f32x2 packed over p-pairs.
// ---------------------------------------------------------------------------
__global__ __launch_bounds__(256, 2) void pre_kernel(
    const int*   __restrict__ sent,
    const float* __restrict__ emb,
    const float* __restrict__ Wx,
    const float* __restrict__ bias)
{
    const int t  = blockIdx.z;
    const int p0 = blockIdx.x * 128;
    const int n0 = blockIdx.y * 128;
    if (p0 >= g_act[t]) return;

    __shared__ int   idxs[128];
    __shared__ __align__(16) float es[20][128];
    __shared__ __align__(16) float ws[20][128];

    const int tid = threadIdx.x;
    const int tx  = tid & 15;
    const int ty  = tid >> 4;

    if (tid < 128) idxs[tid] = sent[g_perm[p0 + tid] * Tv + t];
    __syncthreads();

    ull acc2[8][4];                       // [ni][p-pair]
#pragma unroll
    for (int i = 0; i < 8; i++)
#pragma unroll
        for (int q = 0; q < 4; q++) acc2[i][q] = 0ull;

    for (int k0 = 0; k0 < Dv; k0 += 20) {
        // ws: 640 float4, coalesced LDG.128 -> STS.128
#pragma unroll
        for (int i = 0; i < 3; i++) {
            int idx = i * 256 + tid;
            if (idx < 640) {
                int kl = idx >> 5;
                int nq = idx & 31;
                int n  = n0 + nq * 4;
                float4 v = (n < G4) ? *(const float4*)&Wx[(k0 + kl) * G4 + n]
                                    : make_float4(0.f, 0.f, 0.f, 0.f);
                *(float4*)&ws[kl][nq * 4] = v;
            }
        }
        // es: 640 float4 along k (16B gather), conflict-free transposing STS
#pragma unroll
        for (int i = 0; i < 3; i++) {
            int idx = i * 256 + tid;
            if (idx < 640) {
                int ks = idx >> 7;          // 0..4 (warp-uniform)
                int rl = idx & 127;
                float4 v = *(const float4*)&emb[(size_t)idxs[rl] * Dv + k0 + ks * 4];
                es[ks * 4 + 0][rl] = v.x;
                es[ks * 4 + 1][rl] = v.y;
                es[ks * 4 + 2][rl] = v.z;
                es[ks * 4 + 3][rl] = v.w;
            }
        }
        __syncthreads();
#pragma unroll
        for (int k = 0; k < 20; k++) {
            // a pairs: adjacent floats -> free b64 operands
            ulonglong2 av0 = *(const ulonglong2*)&es[k][tx * 4];
            ulonglong2 av1 = *(const ulonglong2*)&es[k][tx * 4 + 64];
            ull ap[4] = {av0.x, av0.y, av1.x, av1.y};
            float4 w0 = *(const float4*)&ws[k][ty * 4];
            float4 w1 = *(const float4*)&ws[k][ty * 4 + 64];
            float w[8] = {w0.x, w0.y, w0.z, w0.w, w1.x, w1.y, w1.z, w1.w};
#pragma unroll
            for (int ni = 0; ni < 8; ni++) {
                ull wd = pack_dup(w[ni]);
                fma2(acc2[ni][0], wd, ap[0]);
                fma2(acc2[ni][1], wd, ap[1]);
                fma2(acc2[ni][2], wd, ap[2]);
                fma2(acc2[ni][3], wd, ap[3]);
            }
        }
        __syncthreads();
    }

#pragma unroll
    for (int ni = 0; ni < 8; ni++) {
        int n = n0 + (ni >> 2) * 64 + ty * 4 + (ni & 3);
        if (n >= G4) continue;
        float bn = bias[n];
        size_t base = ((size_t)t * G4 + n) * Bv + p0;
        float2 u0 = unpack2(acc2[ni][0]);
        float2 u1 = unpack2(acc2[ni][1]);
        float2 u2 = unpack2(acc2[ni][2]);
        float2 u3 = unpack2(acc2[ni][3]);
        float4 v0 = make_float4(u0.x + bn, u0.y + bn, u1.x + bn, u1.y + bn);
        float4 v1 = make_float4(u2.x + bn, u2.y + bn, u3.x + bn, u3.y + bn);
        __stcs((float4*)&g_xpre[base + tx * 4],      v0);
        __stcs((float4*)&g_xpre[base + tx * 4 + 64], v1);
    }
}

// ---------------------------------------------------------------------------
// Persistent LSTM recurrence: Wh phase-resident, 512 thr, W=16/8 j-tiles,
// f32x2 packed over gate pairs (weights pre-paired in ws4 float4 layout).
// ---------------------------------------------------------------------------
__device__ __forceinline__ float sigmoidf_(float x) {
    return 1.f / (1.f + __expf(-x));
}
__device__ __forceinline__ float tanhf_(float x) {
    return 1.f - 2.f / (__expf(2.f * x) + 1.f);
}

__device__ __forceinline__ void grid_barrier(unsigned target) {
    __threadfence();
    __syncthreads();
    if (threadIdx.x == 0) {
        if (atomicAdd(&g_bar_count, 1u) == NBLK - 1) {
            g_bar_count = 0;
            __threadfence();
            atomicExch(&g_bar_sense, target);
        } else {
            while (*(volatile unsigned*)&g_bar_sense < target) __nanosleep(32);
        }
    }
    __syncthreads();
}

// One tile: 64 p x W j-cols x 4 gates, 512 threads (W=16: PPT=2; W=8: PPT=1).
template<int W>
__device__ __forceinline__ void step_tile_full(
    float hs[2][30][64], const float4* __restrict__ ws4,
    const float* __restrict__ hin, float* __restrict__ hout,
    int t, int p0, int j0, int act)
{
    constexpr int TPJ = NTHR / W;        // 32 or 64
    constexpr int PPT = 64 / TPJ;        // 2 or 1
    const int tid  = threadIdx.x;
    const int pidx = tid % TPJ;
    const int jc   = tid / TPJ;
    const int j    = j0 + jc;
    const bool ldon = tid < 480;         // 480 float4 = 30k x 64p per chunk

    float4 ph;
    auto load_c = [&](int k0) {
        if (ldon)
            ph = __ldcg((const float4*)&hin[(k0 + (tid >> 4)) * Bv + p0
                                            + ((tid & 15) << 2)]);
    };
    auto store_c = [&](int buf) {
        if (ldon)
            *(float4*)&hs[buf][tid >> 4][(tid & 15) << 2] = ph;
    };

    // packed accumulators: acc01 = (gate0, gate1), acc23 = (gate2, gate3)
    ull acc01[PPT], acc23[PPT];
#pragma unroll
    for (int p = 0; p < PPT; p++) { acc01[p] = 0ull; acc23[p] = 0ull; }

    load_c(0);
    store_c(0);
    __syncthreads();

#pragma unroll 1
    for (int c = 0; c < 10; c++) {
        const int cur = c & 1;
        if (c < 9) load_c((c + 1) * 30);
#pragma unroll
        for (int kk = 0; kk < 30; kk++) {
            const int k = c * 30 + kk;
            ulonglong2 wv = *(const ulonglong2*)&ws4[k * W + jc]; // (g0g1),(g2g3)
            if (PPT == 2) {
                float2 h2 = *(const float2*)&hs[cur][kk][pidx * 2];
                ull hh0 = pack_dup(h2.x);
                ull hh1 = pack_dup(h2.y);
                fma2(acc01[0], hh0, wv.x);
                fma2(acc23[0], hh0, wv.y);
                fma2(acc01[1], hh1, wv.x);
                fma2(acc23[1], hh1, wv.y);
            } else {
                ull hh = pack_dup(hs[cur][kk][pidx]);
                fma2(acc01[0], hh, wv.x);
                fma2(acc23[0], hh, wv.y);
            }
        }
        if (c < 9) { store_c(cur ^ 1); __syncthreads(); }
    }

    if (j < Hv) {
        const size_t tb = (size_t)t * G4;
        const int pb = p0 + pidx * PPT;
        const int hi = j * Bv + pb;

        if (PPT == 2 && pb + 2 <= act) {   // fully active: float2 path
            float xp[4][2];
#pragma unroll
            for (int g = 0; g < 4; g++) {
                float2 v = __ldcs((const float2*)&g_xpre[(tb + g * Hv + j) * Bv + pb]);
                xp[g][0] = v.x; xp[g][1] = v.y;
            }
            float2 c2 = __ldcg((const float2*)&g_cT[hi]);
            float cold[2] = {c2.x, c2.y};
            float hn[2], cn[2];
#pragma unroll
            for (int p = 0; p < 2; p++) {
                float2 g01 = unpack2(acc01[p]);
                float2 g23 = unpack2(acc23[p]);
                float iv = sigmoidf_(g01.x + xp[0][p]);
                float fv = sigmoidf_(g01.y + xp[1][p]);
                float gv = tanhf_   (g23.x + xp[2][p]);
                float ov = sigmoidf_(g23.y + xp[3][p]);
                cn[p] = fv * cold[p] + iv * gv;
                hn[p] = ov * tanhf_(cn[p]);
            }
            __stcg((float2*)&hout[hi], make_float2(hn[0], hn[1]));
            __stcg((float2*)&g_cT[hi], make_float2(cn[0], cn[1]));
        } else {                            // straddle / narrow: masked scalar
#pragma unroll
            for (int p = 0; p < PPT; p++) {
                const int pp = pb + p;
                if (pp >= act) continue;
                float2 g01 = unpack2(acc01[p]);
                float2 g23 = unpack2(acc23[p]);
                float gi = g01.x + __ldcs(&g_xpre[(tb + 0 * Hv + j) * Bv + pp]);
                float gf = g01.y + __ldcs(&g_xpre[(tb + 1 * Hv + j) * Bv + pp]);
                float gg = g23.x + __ldcs(&g_xpre[(tb + 2 * Hv + j) * Bv + pp]);
                float go = g23.y + __ldcs(&g_xpre[(tb + 3 * Hv + j) * Bv + pp]);
                float iv = sigmoidf_(gi);
                float fv = sigmoidf_(gf);
                float gv = tanhf_(gg);
                float ov = sigmoidf_(go);
                float cold = __ldcg(&g_cT[hi + p]);
                float cnew = fv * cold + iv * gv;
                float hnew = ov * tanhf_(cnew);
                __stcg(&g_cT[hi + p], cnew);
                __stcg(&hout[hi + p], hnew);
            }
        }
    }
    __syncthreads();   // protect hs before next tile reuses it
}

__global__ __launch_bounds__(NTHR, 2) void lstm_kernel()
{
    extern __shared__ __align__(16) char smem_raw[];
    float4* ws4 = (float4*)smem_raw;                            // 76800 B
    float (*hs)[30][64] = (float(*)[30][64])(smem_raw + 76800); // 15360 B

    const int bid = blockIdx.x;
    const int tid = threadIdx.x;
    int wlast = 0;

#pragma unroll 1
    for (int t = 0; t < Tv; t++) {
        const int act = g_act[t];
        const int na  = (act + 63) >> 6;
        const float* hin  = g_hT[t & 1];
        float*       hout = g_hT[(t & 1) ^ 1];

        int w, njt, lw;
        if (na >= 8) { w = 16; njt = 19; lw = 4; }
        else         { w = 8;  njt = 38; lw = 3; }
        const int jt  = bid % njt;
        const int ptb = bid / njt;
        const int j0  = jt * w;

        if (w != wlast) {    // phase change (happens once): load Wh slice
            for (int idx = tid; idx < 300 * w; idx += NTHR) {
                int k   = idx >> lw;
                int jj  = idx & (w - 1);
                int col = j0 + jj;
                ws4[idx] = (col < Hv) ? g_whT[k * Hv + col]
                                      : make_float4(0.f, 0.f, 0.f, 0.f);
            }
            wlast = w;
            __syncthreads();
        }

        int stride;
        if (w == 16) stride = 15;                   // 285 = 19*15 exact
        else         stride = (jt < 19) ? 8 : 7;    // 285 = 7*38 + 19

        if (w == 16) {
            for (int pp = ptb; pp * 64 < act; pp += stride)
                step_tile_full<16>(hs, ws4, hin, hout, t, pp * 64, j0, act);
        } else {
            for (int pp = ptb; pp * 64 < act; pp += stride)
                step_tile_full<8>(hs, ws4, hin, hout, t, pp * 64, j0, act);
        }
        grid_barrier(t + 1);
    }
}

// ---------------------------------------------------------------------------
// Output: final h for batch b lives in buffer lens[b] & 1 (written at len-1).
// ---------------------------------------------------------------------------
__global__ void out_kernel(const int* __restrict__ lens,
                           const float* __restrict__ Wout,
                           const float* __restrict__ bout,
                           float* __restrict__ out)
{
    int gwarp = (blockIdx.x * blockDim.x + threadIdx.x) >> 5;
    int lane  = threadIdx.x & 31;
    if (gwarp >= Bv) return;

    const int p = g_rank[gwarp];
    const float* hbuf = g_hT[lens[gwarp] & 1];
    float s0 = 0.f, s1 = 0.f, s2 = 0.f;
    for (int jj = lane; jj < Hv; jj += 32) {
        float hv = hbuf[jj * Bv + p];
        s0 = fmaf(hv, Wout[jj * 3 + 0], s0);
        s1 = fmaf(hv, Wout[jj * 3 + 1], s1);
        s2 = fmaf(hv, Wout[jj * 3 + 2], s2);
    }
#pragma unroll
    for (int off = 16; off > 0; off >>= 1) {
        s0 += __shfl_down_sync(0xffffffffu, s0, off);
        s1 += __shfl_down_sync(0xffffffffu, s1, off);
        s2 += __shfl_down_sync(0xffffffffu, s2, off);
    }
    if (lane == 0) {
        out[gwarp * 3 + 0] = s0 + bout[0];
        out[gwarp * 3 + 1] = s1 + bout[1];
        out[gwarp * 3 + 2] = s2 + bout[2];
    }
}

// ---------------------------------------------------------------------------
extern "C" void kernel_launch(void* const* d_in, const int* in_sizes, int n_in,
                              void* d_out, int out_size)
{
    const int*   sent = (const int*)  d_in[0];
    const int*   lens = (const int*)  d_in[1];
    const float* emb  = (const float*)d_in[2];
    const float* Wx   = (const float*)d_in[3];
    const float* Wh   = (const float*)d_in[4];
    const float* bias = (const float*)d_in[5];
    const float* Wout = (const float*)d_in[6];
    const float* bout = (const float*)d_in[7];
    float* out = (float*)d_out;

    cudaFuncSetAttribute(lstm_kernel,
                         cudaFuncAttributeMaxDynamicSharedMemorySize, LSTM_SMEM);

    init_kernel<<<1, 1024>>>(lens);
    zero_kernel<<<(Hv * Bv + 255) / 256, 256>>>();
    trans_kernel<<<(Hv * Hv + 255) / 256, 256>>>(Wh);

    dim3 pg(Bv / 128, (G4 + 127) / 128, Tv);   // 8 x 10 x 80
    pre_kernel<<<pg, 256>>>(sent, emb, Wx, bias);

    // one persistent launch for all 80 timesteps
    lstm_kernel<<<NBLK, NTHR, LSTM_SMEM>>>();

    out_kernel<<<(Bv * 32 + 127) / 128, 128>>>(lens, Wout, bout, out);
}